// round 4
// baseline (speedup 1.0000x reference)
#include <cuda_runtime.h>

// ---------------------------------------------------------------------------
// out[t,:] = b + ( Σ_{e->t} f[src_e] ⊗ Y_e ).reshape(512) @ W
// Phase 1: counting-sort by target; scatter writes sorted payload {src, Y[16]}
// Phase 2: accum: warp per target, f32x2 FMA, M[t,h,i] in registers
// Phase 3: tiled GEMM with f32x2 (target-pairs) M[50000,512] @ W[512,32] + b
// ---------------------------------------------------------------------------

#define MAX_ATOMS 50016
#define MAX_EDGES 800000
#define SCAN_TILE 256

__device__ float g_M[(size_t)MAX_ATOMS * 512];     // ~102 MB scratch
__device__ float g_Ys[(size_t)MAX_EDGES * 16];     // sorted Y payload, 51 MB
__device__ int   g_ssrc[MAX_EDGES];                // sorted sources
__device__ int   g_cnt[MAX_ATOMS + 1];
__device__ int   g_start[MAX_ATOMS + 1];
__device__ int   g_cur[MAX_ATOMS + 1];
__device__ int   g_bsum[256];
__device__ int   g_boff[256];
__device__ int   g_is64;

// ---- f32x2 helpers --------------------------------------------------------
__device__ __forceinline__ unsigned long long ffma2(unsigned long long a,
                                                    unsigned long long b,
                                                    unsigned long long c) {
    unsigned long long d;
    asm("fma.rn.f32x2 %0, %1, %2, %3;" : "=l"(d) : "l"(a), "l"(b), "l"(c));
    return d;
}
__device__ __forceinline__ unsigned long long splat2(float x) {
    unsigned long long d;
    unsigned int xb = __float_as_uint(x);
    asm("mov.b64 %0, {%1, %1};" : "=l"(d) : "r"(xb));
    return d;
}
__device__ __forceinline__ float lo2(unsigned long long v) {
    return __uint_as_float((unsigned int)v);
}
__device__ __forceinline__ float hi2(unsigned long long v) {
    return __uint_as_float((unsigned int)(v >> 32));
}

// --- prep: zero counts; block 0 detects int64-vs-int32 edge_index ----------
__global__ void prep_kernel(const unsigned int* __restrict__ idx_words,
                            int nwords_check, int n_atoms) {
    int gid = blockIdx.x * blockDim.x + threadIdx.x;
    for (int i = gid; i <= n_atoms; i += gridDim.x * blockDim.x) g_cnt[i] = 0;

    if (blockIdx.x == 0) {
        __shared__ unsigned int red[256];
        unsigned int acc = 0;
        for (int w = 1 + 2 * (int)threadIdx.x; w < nwords_check; w += 2 * (int)blockDim.x)
            acc |= idx_words[w];
        red[threadIdx.x] = acc;
        __syncthreads();
        for (int s = 128; s > 0; s >>= 1) {
            if ((int)threadIdx.x < s) red[threadIdx.x] |= red[threadIdx.x + s];
            __syncthreads();
        }
        if (threadIdx.x == 0) g_is64 = (red[0] == 0u) ? 1 : 0;
    }
}

// --- histogram of targets --------------------------------------------------
__global__ void hist_kernel(const int* __restrict__ idx, int n_edges) {
    const int stride = g_is64 ? 2 : 1;
    const int* __restrict__ tb = idx + (size_t)n_edges * stride;
    int gid = blockIdx.x * blockDim.x + threadIdx.x;
    for (int e = gid; e < n_edges; e += gridDim.x * blockDim.x)
        atomicAdd(&g_cnt[tb[(size_t)e * stride]], 1);
}

// --- scan phase A: per-tile exclusive scan + tile total --------------------
__global__ void scanA_kernel(int n_atoms) {
    __shared__ int s[SCAN_TILE];
    const int tid = threadIdx.x;
    const int i = blockIdx.x * SCAN_TILE + tid;
    int v = (i < n_atoms) ? g_cnt[i] : 0;
    s[tid] = v;
    __syncthreads();
    int val = v;
    for (int d = 1; d < SCAN_TILE; d <<= 1) {
        int add = (tid >= d) ? s[tid - d] : 0;
        __syncthreads();
        s[tid] += add;
        __syncthreads();
    }
    // exclusive within tile
    if (i <= n_atoms) g_start[i] = s[tid] - val;
    if (tid == SCAN_TILE - 1) g_bsum[blockIdx.x] = s[tid];
}

// --- scan phase B: scan tile totals (ntiles <= 256) ------------------------
__global__ void scanB_kernel(int ntiles, int n_atoms, int n_edges) {
    __shared__ int s[256];
    const int tid = threadIdx.x;
    int v = (tid < ntiles) ? g_bsum[tid] : 0;
    s[tid] = v;
    __syncthreads();
    for (int d = 1; d < 256; d <<= 1) {
        int add = (tid >= d) ? s[tid - d] : 0;
        __syncthreads();
        s[tid] += add;
        __syncthreads();
    }
    if (tid < ntiles) g_boff[tid] = s[tid] - v;   // exclusive
    if (tid == 0) {
        g_start[n_atoms] = n_edges;
        g_cur[n_atoms]   = n_edges;
    }
}

// --- scan phase C: add tile offsets, init cur ------------------------------
__global__ void scanC_kernel(int n_atoms) {
    const int i = blockIdx.x * SCAN_TILE + threadIdx.x;
    if (i < n_atoms) {
        int st = g_start[i] + g_boff[blockIdx.x];
        g_start[i] = st;
        g_cur[i]   = st;
    }
}

// --- scatter: compute Y, write sorted payload {src, Y[16]} -----------------
__global__ void scatter_kernel(const int* __restrict__ idx,
                               const float* __restrict__ ev, int n_edges) {
    const int stride = g_is64 ? 2 : 1;
    const int* __restrict__ sb = idx;
    const int* __restrict__ tb = idx + (size_t)n_edges * stride;
    int gid = blockIdx.x * blockDim.x + threadIdx.x;
    for (int e = gid; e < n_edges; e += gridDim.x * blockDim.x) {
        const int src = sb[(size_t)e * stride];
        const int tgt = tb[(size_t)e * stride];
        const int pos = atomicAdd(&g_cur[tgt], 1);

        const float vx = ev[(size_t)e * 3 + 0];
        const float vy = ev[(size_t)e * 3 + 1];
        const float vz = ev[(size_t)e * 3 + 2];
        const float r  = sqrtf(vx * vx + vy * vy + vz * vz);
        const float inv = 1.0f / fmaxf(r, 1e-12f);
        const float x = vx * inv, y = vy * inv, z = vz * inv;
        const float x2 = x * x, y2 = y * y, z2 = z * z;

        float4* __restrict__ dst = reinterpret_cast<float4*>(g_Ys + (size_t)pos * 16);
        dst[0] = make_float4(0.28209479177387814f,
                             0.4886025119029199f * y,
                             0.4886025119029199f * z,
                             0.4886025119029199f * x);
        dst[1] = make_float4(1.0925484305920792f * x * y,
                             1.0925484305920792f * y * z,
                             0.31539156525252005f * (3.0f * z2 - 1.0f),
                             1.0925484305920792f * x * z);
        dst[2] = make_float4(0.5462742152960396f * (x2 - y2),
                             0.5900435899266435f * y * (3.0f * x2 - y2),
                             2.890611442640554f * x * y * z,
                             0.4570457994644658f * y * (5.0f * z2 - 1.0f));
        dst[3] = make_float4(0.3731763325901154f * z * (5.0f * z2 - 3.0f),
                             0.4570457994644658f * x * (5.0f * z2 - 1.0f),
                             1.445305721320277f * z * (x2 - y2),
                             0.5900435899266435f * x * (x2 - 3.0f * y2));
        g_ssrc[pos] = src;
    }
}

// --- accum: warp per target; lane = h; f32x2 accumulation ------------------
__global__ void accum_kernel(const float* __restrict__ f, int n_atoms) {
    const int lane = threadIdx.x & 31;
    const int t = (int)((blockIdx.x * blockDim.x + threadIdx.x) >> 5);
    if (t >= n_atoms) return;

    const int start = g_start[t];
    const int end   = g_start[t + 1];

    unsigned long long m[8];
#pragma unroll
    for (int i = 0; i < 8; i++) m[i] = 0ull;

    if (start < end) {
        int   src = g_ssrc[start];
        float fh  = __ldg(f + (size_t)src * 32 + lane);

        for (int p = start; p < end; p++) {
            const int pn = (p + 1 < end) ? (p + 1) : p;
            const int   src_n = g_ssrc[pn];
            const float fh_n  = __ldg(f + (size_t)src_n * 32 + lane);

            const unsigned long long fh2 = splat2(fh);
            const ulonglong2* __restrict__ yv =
                reinterpret_cast<const ulonglong2*>(g_Ys + (size_t)p * 16);
            const ulonglong2 y0 = yv[0], y1 = yv[1], y2 = yv[2], y3 = yv[3];

            m[0] = ffma2(fh2, y0.x, m[0]);  m[1] = ffma2(fh2, y0.y, m[1]);
            m[2] = ffma2(fh2, y1.x, m[2]);  m[3] = ffma2(fh2, y1.y, m[3]);
            m[4] = ffma2(fh2, y2.x, m[4]);  m[5] = ffma2(fh2, y2.y, m[5]);
            m[6] = ffma2(fh2, y3.x, m[6]);  m[7] = ffma2(fh2, y3.y, m[7]);

            fh = fh_n;
        }
    }

    ulonglong2* dst = reinterpret_cast<ulonglong2*>(g_M + (size_t)t * 512 + lane * 16);
    dst[0] = make_ulonglong2(m[0], m[1]);
    dst[1] = make_ulonglong2(m[2], m[3]);
    dst[2] = make_ulonglong2(m[4], m[5]);
    dst[3] = make_ulonglong2(m[6], m[7]);
}

// --- GEMM: out[t,c] = b[c] + sum_k M[t,k]*W[k,c], f32x2 over target pairs --
// Block: 128 threads, tile = 64 targets x 32 c, each thread 4t x 4c.
#define GT 64
#define MS_STRIDE 66
__global__ void gemm_kernel(const float* __restrict__ W,
                            const float* __restrict__ b,
                            float* __restrict__ out, int n_atoms) {
    __shared__ float Ms[32][MS_STRIDE];           // [kk][t], kk-major
    __shared__ unsigned long long Wd[32][32];     // duplicated (w,w) pairs

    const int tid = threadIdx.x;       // 0..127
    const int tx  = tid & 7;           // c group (4 c each)
    const int ty  = tid >> 3;          // t group (4 t each), 0..15
    const int t0  = blockIdx.x * GT;

    unsigned long long acc01[4], acc23[4];   // (t0,t1) and (t2,t3) pairs x 4c
#pragma unroll
    for (int i = 0; i < 4; i++) { acc01[i] = 0ull; acc23[i] = 0ull; }

    for (int k0 = 0; k0 < 512; k0 += 32) {
        __syncthreads();
        // load + transpose M tile: [64 t][32 k] -> Ms[kk][t]
#pragma unroll
        for (int v = tid; v < GT * 8; v += 128) {
            const int row  = v >> 3;       // t within tile
            const int col4 = v & 7;        // k/4 within chunk
            float4 val = make_float4(0.f, 0.f, 0.f, 0.f);
            const int t = t0 + row;
            if (t < n_atoms)
                val = *reinterpret_cast<const float4*>(
                    g_M + (size_t)t * 512 + k0 + col4 * 4);
            Ms[col4 * 4 + 0][row] = val.x;
            Ms[col4 * 4 + 1][row] = val.y;
            Ms[col4 * 4 + 2][row] = val.z;
            Ms[col4 * 4 + 3][row] = val.w;
        }
        // load W chunk, duplicate into (w,w) u64 pairs
#pragma unroll
        for (int v = tid; v < 32 * 8; v += 128) {
            const int row  = v >> 3;
            const int col4 = v & 7;
            float4 val = *reinterpret_cast<const float4*>(
                W + (size_t)(k0 + row) * 32 + col4 * 4);
            Wd[row][col4 * 4 + 0] = splat2(val.x);
            Wd[row][col4 * 4 + 1] = splat2(val.y);
            Wd[row][col4 * 4 + 2] = splat2(val.z);
            Wd[row][col4 * 4 + 3] = splat2(val.w);
        }
        __syncthreads();

#pragma unroll
        for (int kk = 0; kk < 32; kk++) {
            const unsigned long long a01 =
                *reinterpret_cast<const unsigned long long*>(&Ms[kk][ty * 4]);
            const unsigned long long a23 =
                *reinterpret_cast<const unsigned long long*>(&Ms[kk][ty * 4 + 2]);
            const ulonglong2 w01 =
                *reinterpret_cast<const ulonglong2*>(&Wd[kk][tx * 4]);
            const ulonglong2 w23 =
                *reinterpret_cast<const ulonglong2*>(&Wd[kk][tx * 4 + 2]);
            acc01[0] = ffma2(a01, w01.x, acc01[0]);
            acc01[1] = ffma2(a01, w01.y, acc01[1]);
            acc01[2] = ffma2(a01, w23.x, acc01[2]);
            acc01[3] = ffma2(a01, w23.y, acc01[3]);
            acc23[0] = ffma2(a23, w01.x, acc23[0]);
            acc23[1] = ffma2(a23, w01.y, acc23[1]);
            acc23[2] = ffma2(a23, w23.x, acc23[2]);
            acc23[3] = ffma2(a23, w23.y, acc23[3]);
        }
    }

    const float4 bv = *reinterpret_cast<const float4*>(b + tx * 4);
    const int tb0 = t0 + ty * 4;
    if (tb0 + 0 < n_atoms) {
        float4 o = make_float4(lo2(acc01[0]) + bv.x, lo2(acc01[1]) + bv.y,
                               lo2(acc01[2]) + bv.z, lo2(acc01[3]) + bv.w);
        *reinterpret_cast<float4*>(out + (size_t)(tb0 + 0) * 32 + tx * 4) = o;
    }
    if (tb0 + 1 < n_atoms) {
        float4 o = make_float4(hi2(acc01[0]) + bv.x, hi2(acc01[1]) + bv.y,
                               hi2(acc01[2]) + bv.z, hi2(acc01[3]) + bv.w);
        *reinterpret_cast<float4*>(out + (size_t)(tb0 + 1) * 32 + tx * 4) = o;
    }
    if (tb0 + 2 < n_atoms) {
        float4 o = make_float4(lo2(acc23[0]) + bv.x, lo2(acc23[1]) + bv.y,
                               lo2(acc23[2]) + bv.z, lo2(acc23[3]) + bv.w);
        *reinterpret_cast<float4*>(out + (size_t)(tb0 + 2) * 32 + tx * 4) = o;
    }
    if (tb0 + 3 < n_atoms) {
        float4 o = make_float4(hi2(acc23[0]) + bv.x, hi2(acc23[1]) + bv.y,
                               hi2(acc23[2]) + bv.z, hi2(acc23[3]) + bv.w);
        *reinterpret_cast<float4*>(out + (size_t)(tb0 + 3) * 32 + tx * 4) = o;
    }
}

extern "C" void kernel_launch(void* const* d_in, const int* in_sizes, int n_in,
                              void* d_out, int out_size) {
    const float* f   = (const float*)d_in[0];   // [n_atoms,32]
    const float* ev  = (const float*)d_in[1];   // [n_edges,3]
    const int*   idx = (const int*)d_in[2];     // [2,n_edges] int32 or int64
    const float* W   = (const float*)d_in[3];   // [512,32]
    const float* b   = (const float*)d_in[4];   // [32]
    float* out = (float*)d_out;

    const int n_atoms = in_sizes[0] / 32;
    const int n_edges = in_sizes[1] / 3;

    int ncheck = 2 * n_edges;
    if (ncheck > 8192) ncheck = 8192;

    const int ntiles = (n_atoms + SCAN_TILE - 1) / SCAN_TILE;

    prep_kernel<<<128, 256>>>((const unsigned int*)idx, ncheck, n_atoms);
    hist_kernel<<<1184, 256>>>(idx, n_edges);
    scanA_kernel<<<ntiles, SCAN_TILE>>>(n_atoms);
    scanB_kernel<<<1, 256>>>(ntiles, n_atoms, n_edges);
    scanC_kernel<<<ntiles, SCAN_TILE>>>(n_atoms);
    scatter_kernel<<<1184, 256>>>(idx, ev, n_edges);

    const int ablocks = (n_atoms * 32 + 255) / 256;
    accum_kernel<<<ablocks, 256>>>(f, n_atoms);

    const int gblocks = (n_atoms + GT - 1) / GT;
    gemm_kernel<<<gblocks, 128>>>(W, b, out, n_atoms);
}

// round 5
// speedup vs baseline: 1.0086x; 1.0086x over previous
#include <cuda_runtime.h>
#include <cstdio>

// ---------------------------------------------------------------------------
// out[t,:] = b + ( Σ_{e->t} f[src_e] ⊗ Y_e ).reshape(512) @ W
//   hist(0) -> lookback-scan(1) -> scatter{ev,src} sorted (2) -> accum(3)
//   -> gemm(4) -> cleanup+report(5)
// g_cnt/g_desc are zeroed by cleanup at the END of each call (and statically
// zero-initialized for the first call) so every call does identical work.
// ---------------------------------------------------------------------------

#define MAX_ATOMS 50016
#define MAX_EDGES 800000

__device__ float  g_M[(size_t)MAX_ATOMS * 512];      // ~102 MB scratch
__device__ float4 g_pay[MAX_EDGES];                  // sorted {evx,evy,evz,src}
__device__ int    g_cnt[MAX_ATOMS + 1];              // zero at call start
__device__ int    g_start[MAX_ATOMS + 1];
__device__ int    g_cur[MAX_ATOMS + 1];
__device__ unsigned long long g_desc[512];           // zero at call start
__device__ unsigned long long g_ts[8];

#define ST_AGG (1ull << 62)
#define ST_INC (2ull << 62)
#define ST_VAL 0x3FFFFFFFFFFFFFFFull

static __device__ __forceinline__ unsigned long long gtimer() {
    unsigned long long t;
    asm volatile("mov.u64 %0, %%globaltimer;" : "=l"(t));
    return t;
}

// per-warp int64 detection: odd 32-bit words all zero <=> int64 high halves
static __device__ __forceinline__ int is64_detect(const unsigned int* __restrict__ w) {
    const int lane = threadIdx.x & 31;
    unsigned int v = w[1 + 2 * lane] | w[65 + 2 * lane];
    return __all_sync(0xFFFFFFFFu, v == 0u);
}

// ---- f32x2 helpers (gemm) -------------------------------------------------
__device__ __forceinline__ unsigned long long ffma2(unsigned long long a,
                                                    unsigned long long b,
                                                    unsigned long long c) {
    unsigned long long d;
    asm("fma.rn.f32x2 %0, %1, %2, %3;" : "=l"(d) : "l"(a), "l"(b), "l"(c));
    return d;
}
__device__ __forceinline__ unsigned long long splat2(float x) {
    unsigned long long d;
    unsigned int xb = __float_as_uint(x);
    asm("mov.b64 %0, {%1, %1};" : "=l"(d) : "r"(xb));
    return d;
}
__device__ __forceinline__ float lo2(unsigned long long v) {
    return __uint_as_float((unsigned int)v);
}
__device__ __forceinline__ float hi2(unsigned long long v) {
    return __uint_as_float((unsigned int)(v >> 32));
}

// --- k0: histogram of targets (g_cnt pre-zeroed) ---------------------------
__global__ void hist_kernel(const int* __restrict__ idx, int n_edges) {
    if (blockIdx.x == 0 && threadIdx.x == 0) g_ts[0] = gtimer();
    const int is64 = is64_detect((const unsigned int*)idx);
    const int stride = is64 ? 2 : 1;
    const int* __restrict__ tb = idx + (size_t)n_edges * stride;
    int gid = blockIdx.x * blockDim.x + threadIdx.x;
    for (int e = gid; e < n_edges; e += gridDim.x * blockDim.x)
        atomicAdd(&g_cnt[tb[(size_t)e * stride]], 1);
}

// --- k1: single-pass exclusive scan (decoupled lookback) -------------------
__global__ void scan_kernel(int n_atoms, int n_edges) {
    if (blockIdx.x == 0 && threadIdx.x == 0) g_ts[1] = gtimer();
    __shared__ int s[256];
    __shared__ int s_excl;
    const int tid = threadIdx.x;
    const int b   = blockIdx.x;
    const int i   = b * 256 + tid;

    int v = (i < n_atoms) ? g_cnt[i] : 0;
    s[tid] = v;
    __syncthreads();
    const int val = v;
    for (int d = 1; d < 256; d <<= 1) {
        int a = (tid >= d) ? s[tid - d] : 0;
        __syncthreads();
        s[tid] += a;
        __syncthreads();
    }
    const int incl  = s[tid];
    const int total = s[255];

    if (tid == 0) {
        if (b == 0) {
            atomicExch(&g_desc[0], ST_INC | (unsigned long long)total);
            s_excl = 0;
        } else {
            atomicExch(&g_desc[b], ST_AGG | (unsigned long long)total);
            long long run = 0;
            int j = b - 1;
            while (true) {
                unsigned long long d = atomicAdd(&g_desc[j], 0ull);
                unsigned long long st = d >> 62;
                if (st == 0ull) { __nanosleep(40); continue; }
                run += (long long)(d & ST_VAL);
                if (st == 2ull) break;
                j--;
            }
            atomicExch(&g_desc[b], ST_INC | (unsigned long long)(run + total));
            s_excl = (int)run;
        }
        if (b == 0) {
            g_start[n_atoms] = n_edges;
            g_cur[n_atoms]   = n_edges;
        }
    }
    __syncthreads();
    if (i < n_atoms) {
        const int st = s_excl + incl - val;
        g_start[i] = st;
        g_cur[i]   = st;
    }
}

// --- k2: scatter sorted payload {ev.xyz, src} ------------------------------
__global__ void scatter_kernel(const int* __restrict__ idx,
                               const float* __restrict__ ev, int n_edges) {
    if (blockIdx.x == 0 && threadIdx.x == 0) g_ts[2] = gtimer();
    const int is64 = is64_detect((const unsigned int*)idx);
    const int stride = is64 ? 2 : 1;
    const int* __restrict__ sb = idx;
    const int* __restrict__ tb = idx + (size_t)n_edges * stride;
    int gid = blockIdx.x * blockDim.x + threadIdx.x;
    for (int e = gid; e < n_edges; e += gridDim.x * blockDim.x) {
        const int src = sb[(size_t)e * stride];
        const int tgt = tb[(size_t)e * stride];
        const int pos = atomicAdd(&g_cur[tgt], 1);
        g_pay[pos] = make_float4(ev[(size_t)e * 3 + 0],
                                 ev[(size_t)e * 3 + 1],
                                 ev[(size_t)e * 3 + 2],
                                 __int_as_float(src));
    }
}

// --- k3: accum: warp per target; lane = h; depth-2 decoupled prefetch ------
__global__ void accum_kernel(const float* __restrict__ f, int n_atoms) {
    if (blockIdx.x == 0 && threadIdx.x == 0) g_ts[3] = gtimer();
    const int lane = threadIdx.x & 31;
    const int t = (int)((blockIdx.x * blockDim.x + threadIdx.x) >> 5);
    if (t >= n_atoms) return;

    const int start = g_start[t];
    const int end   = g_start[t + 1];

    float m[16];
#pragma unroll
    for (int i = 0; i < 16; i++) m[i] = 0.f;

    if (start < end) {
        float4 pc = g_pay[start];
        int    sc = __float_as_int(pc.w);
        float  fc = __ldg(f + (size_t)sc * 32 + lane);

        for (int p = start; p < end; p++) {
            // prefetch next payload + next f row (independent of this iter's use)
            const int    pn  = (p + 1 < end) ? (p + 1) : p;
            const float4 pnx = g_pay[pn];
            const int    sn  = __float_as_int(pnx.w);
            const float  fn  = __ldg(f + (size_t)sn * 32 + lane);

            const float vx = pc.x, vy = pc.y, vz = pc.z;
            const float r   = sqrtf(vx * vx + vy * vy + vz * vz);
            const float inv = 1.0f / fmaxf(r, 1e-12f);
            const float x = vx * inv, y = vy * inv, z = vz * inv;
            const float x2 = x * x, y2 = y * y, z2 = z * z;

            m[0]  = fmaf(fc, 0.28209479177387814f, m[0]);
            m[1]  = fmaf(fc, 0.4886025119029199f * y, m[1]);
            m[2]  = fmaf(fc, 0.4886025119029199f * z, m[2]);
            m[3]  = fmaf(fc, 0.4886025119029199f * x, m[3]);
            m[4]  = fmaf(fc, 1.0925484305920792f * x * y, m[4]);
            m[5]  = fmaf(fc, 1.0925484305920792f * y * z, m[5]);
            m[6]  = fmaf(fc, 0.31539156525252005f * (3.0f * z2 - 1.0f), m[6]);
            m[7]  = fmaf(fc, 1.0925484305920792f * x * z, m[7]);
            m[8]  = fmaf(fc, 0.5462742152960396f * (x2 - y2), m[8]);
            m[9]  = fmaf(fc, 0.5900435899266435f * y * (3.0f * x2 - y2), m[9]);
            m[10] = fmaf(fc, 2.890611442640554f * x * y * z, m[10]);
            m[11] = fmaf(fc, 0.4570457994644658f * y * (5.0f * z2 - 1.0f), m[11]);
            m[12] = fmaf(fc, 0.3731763325901154f * z * (5.0f * z2 - 3.0f), m[12]);
            m[13] = fmaf(fc, 0.4570457994644658f * x * (5.0f * z2 - 1.0f), m[13]);
            m[14] = fmaf(fc, 1.445305721320277f * z * (x2 - y2), m[14]);
            m[15] = fmaf(fc, 0.5900435899266435f * x * (x2 - 3.0f * y2), m[15]);

            pc = pnx;
            fc = fn;
        }
    }

    float4* dst = reinterpret_cast<float4*>(g_M + (size_t)t * 512 + lane * 16);
    dst[0] = make_float4(m[0],  m[1],  m[2],  m[3]);
    dst[1] = make_float4(m[4],  m[5],  m[6],  m[7]);
    dst[2] = make_float4(m[8],  m[9],  m[10], m[11]);
    dst[3] = make_float4(m[12], m[13], m[14], m[15]);
}

// --- k4: GEMM out[t,c] = b[c] + sum_k M[t,k]*W[k,c], f32x2 target pairs ----
#define GT 64
#define MS_STRIDE 66
__global__ void gemm_kernel(const float* __restrict__ W,
                            const float* __restrict__ b,
                            float* __restrict__ out, int n_atoms) {
    if (blockIdx.x == 0 && threadIdx.x == 0) g_ts[4] = gtimer();
    __shared__ float Ms[32][MS_STRIDE];           // [kk][t], kk-major
    __shared__ unsigned long long Wd[32][32];     // duplicated (w,w) pairs

    const int tid = threadIdx.x;       // 0..127
    const int tx  = tid & 7;           // c group (4 c each)
    const int ty  = tid >> 3;          // t group (4 t each), 0..15
    const int t0  = blockIdx.x * GT;

    unsigned long long acc01[4], acc23[4];
#pragma unroll
    for (int i = 0; i < 4; i++) { acc01[i] = 0ull; acc23[i] = 0ull; }

    for (int k0 = 0; k0 < 512; k0 += 32) {
        __syncthreads();
#pragma unroll
        for (int v = tid; v < GT * 8; v += 128) {
            const int row  = v >> 3;
            const int col4 = v & 7;
            float4 val = make_float4(0.f, 0.f, 0.f, 0.f);
            const int t = t0 + row;
            if (t < n_atoms)
                val = *reinterpret_cast<const float4*>(
                    g_M + (size_t)t * 512 + k0 + col4 * 4);
            Ms[col4 * 4 + 0][row] = val.x;
            Ms[col4 * 4 + 1][row] = val.y;
            Ms[col4 * 4 + 2][row] = val.z;
            Ms[col4 * 4 + 3][row] = val.w;
        }
#pragma unroll
        for (int v = tid; v < 32 * 8; v += 128) {
            const int row  = v >> 3;
            const int col4 = v & 7;
            float4 val = *reinterpret_cast<const float4*>(
                W + (size_t)(k0 + row) * 32 + col4 * 4);
            Wd[row][col4 * 4 + 0] = splat2(val.x);
            Wd[row][col4 * 4 + 1] = splat2(val.y);
            Wd[row][col4 * 4 + 2] = splat2(val.z);
            Wd[row][col4 * 4 + 3] = splat2(val.w);
        }
        __syncthreads();

#pragma unroll
        for (int kk = 0; kk < 32; kk++) {
            const unsigned long long a01 =
                *reinterpret_cast<const unsigned long long*>(&Ms[kk][ty * 4]);
            const unsigned long long a23 =
                *reinterpret_cast<const unsigned long long*>(&Ms[kk][ty * 4 + 2]);
            const ulonglong2 w01 =
                *reinterpret_cast<const ulonglong2*>(&Wd[kk][tx * 4]);
            const ulonglong2 w23 =
                *reinterpret_cast<const ulonglong2*>(&Wd[kk][tx * 4 + 2]);
            acc01[0] = ffma2(a01, w01.x, acc01[0]);
            acc01[1] = ffma2(a01, w01.y, acc01[1]);
            acc01[2] = ffma2(a01, w23.x, acc01[2]);
            acc01[3] = ffma2(a01, w23.y, acc01[3]);
            acc23[0] = ffma2(a23, w01.x, acc23[0]);
            acc23[1] = ffma2(a23, w01.y, acc23[1]);
            acc23[2] = ffma2(a23, w23.x, acc23[2]);
            acc23[3] = ffma2(a23, w23.y, acc23[3]);
        }
    }

    const float4 bv = *reinterpret_cast<const float4*>(b + tx * 4);
    const int tb0 = t0 + ty * 4;
    if (tb0 + 0 < n_atoms) {
        float4 o = make_float4(lo2(acc01[0]) + bv.x, lo2(acc01[1]) + bv.y,
                               lo2(acc01[2]) + bv.z, lo2(acc01[3]) + bv.w);
        *reinterpret_cast<float4*>(out + (size_t)(tb0 + 0) * 32 + tx * 4) = o;
    }
    if (tb0 + 1 < n_atoms) {
        float4 o = make_float4(hi2(acc01[0]) + bv.x, hi2(acc01[1]) + bv.y,
                               hi2(acc01[2]) + bv.z, hi2(acc01[3]) + bv.w);
        *reinterpret_cast<float4*>(out + (size_t)(tb0 + 1) * 32 + tx * 4) = o;
    }
    if (tb0 + 2 < n_atoms) {
        float4 o = make_float4(lo2(acc23[0]) + bv.x, lo2(acc23[1]) + bv.y,
                               lo2(acc23[2]) + bv.z, lo2(acc23[3]) + bv.w);
        *reinterpret_cast<float4*>(out + (size_t)(tb0 + 2) * 32 + tx * 4) = o;
    }
    if (tb0 + 3 < n_atoms) {
        float4 o = make_float4(hi2(acc23[0]) + bv.x, hi2(acc23[1]) + bv.y,
                               hi2(acc23[2]) + bv.z, hi2(acc23[3]) + bv.w);
        *reinterpret_cast<float4*>(out + (size_t)(tb0 + 3) * 32 + tx * 4) = o;
    }
}

// --- k5: cleanup (re-zero state for next call) + phase report --------------
__global__ void cleanup_kernel(int n_atoms) {
    if (blockIdx.x == 0 && threadIdx.x == 0) g_ts[5] = gtimer();
    int gid = blockIdx.x * blockDim.x + threadIdx.x;
    for (int i = gid; i <= n_atoms; i += gridDim.x * blockDim.x) g_cnt[i] = 0;
    for (int i = gid; i < 512; i += gridDim.x * blockDim.x) g_desc[i] = 0ull;
    if (blockIdx.x == 0 && threadIdx.x == 0) {
        printf("PHASES_ns hist=%llu scan=%llu scatter=%llu accum=%llu gemm=%llu\n",
               g_ts[1] - g_ts[0], g_ts[2] - g_ts[1], g_ts[3] - g_ts[2],
               g_ts[4] - g_ts[3], g_ts[5] - g_ts[4]);
    }
}

extern "C" void kernel_launch(void* const* d_in, const int* in_sizes, int n_in,
                              void* d_out, int out_size) {
    const float* f   = (const float*)d_in[0];   // [n_atoms,32]
    const float* ev  = (const float*)d_in[1];   // [n_edges,3]
    const int*   idx = (const int*)d_in[2];     // [2,n_edges] int32 or int64
    const float* W   = (const float*)d_in[3];   // [512,32]
    const float* b   = (const float*)d_in[4];   // [32]
    float* out = (float*)d_out;

    const int n_atoms = in_sizes[0] / 32;
    const int n_edges = in_sizes[1] / 3;

    const int sblocks = (n_atoms + 255) / 256;

    hist_kernel<<<1184, 256>>>(idx, n_edges);
    scan_kernel<<<sblocks, 256>>>(n_atoms, n_edges);
    scatter_kernel<<<1184, 256>>>(idx, ev, n_edges);

    const int ablocks = (n_atoms * 32 + 255) / 256;
    accum_kernel<<<ablocks, 256>>>(f, n_atoms);

    const int gblocks = (n_atoms + GT - 1) / GT;
    gemm_kernel<<<gblocks, 128>>>(W, b, out, n_atoms);

    cleanup_kernel<<<128, 256>>>(n_atoms);
}